// round 13
// baseline (speedup 1.0000x reference)
#include <cuda_runtime.h>

#define B_   256
#define N_   64
#define K_   12
#define D_   128
#define ROWS 16384

__device__ __forceinline__ float dot4(float4 a, float4 b) {
    return fmaf(a.x, b.x, fmaf(a.y, b.y, fmaf(a.z, b.z, a.w * b.w)));
}
__device__ __forceinline__ void ffma2(unsigned long long& d, unsigned long long a, unsigned long long b) {
    asm("fma.rn.f32x2 %0, %1, %2, %0;" : "+l"(d) : "l"(a), "l"(b));
}
__device__ __forceinline__ unsigned long long pack2(float x) {
    unsigned long long r;
    asm("mov.b64 %0, {%1, %1};" : "=l"(r) : "f"(x));
    return r;
}
__device__ __forceinline__ float2 unpack2(unsigned long long v) {
    float2 f;
    asm("mov.b64 {%0, %1}, %2;" : "=f"(f.x), "=f"(f.y) : "l"(v));
    return f;
}

// ---------------- single fused kernel ---------------------------------------
// 128 blocks x 512 threads, 1 block/SM, single wave.
// Block: [Wv->smem || redundant uq/uk/c] -> syncthreads ->
// attn: quarter-warp per row (warp = 4 rows concurrent, 2 iterations) ->
// GEMM: warp = 8 rows x 128 cols from its own as_s slice (syncwarp only).
#define F_THREADS 512
#define F_TILE    128
// floats: Wv 16384 + As 16384 + uq 128 + uk 128 + ssum 128 + c 4
#define F_SM_FLOATS (16384 + 16384 + 128 + 128 + 128 + 4)

__global__ __launch_bounds__(F_THREADS, 1)
void gat_fused(const float* __restrict__ nodes, const float* __restrict__ nbrs,
               const float* __restrict__ mask,
               const float* __restrict__ Wq, const float* __restrict__ bq,
               const float* __restrict__ Wk, const float* __restrict__ bk,
               const float* __restrict__ Wv, const float* __restrict__ bv,
               const float* __restrict__ waq, const float* __restrict__ wak,
               const float* __restrict__ ba,
               float* __restrict__ out)
{
    extern __shared__ float sm[];
    float* wv_s   = sm;                    // [128][128]
    float* as_s   = sm + 16384;            // [128][128]
    float* uq_s   = as_s + 16384;          // [128]
    float* uk_s   = uq_s + 128;            // [128]
    float* ssum_s = uk_s + 128;            // [128]
    float* c_s    = ssum_s + 128;          // [1]

    const int tid  = threadIdx.x;
    const int lane = tid & 31;
    const int wm   = tid >> 5;             // 0..15
    const int row0 = blockIdx.x * F_TILE;

    // ---- Wv -> shared (issued first; drains by the syncthreads) ----
    {
        const float4* src = (const float4*)Wv;
        float4* dst = (float4*)wv_s;
#pragma unroll
        for (int i = tid; i < 16384 / 4; i += F_THREADS) dst[i] = src[i];
    }

    // ---- redundant per-block prologue: uq = Wq@waq, uk = Wk@wak, c ----
    {
        float4 waq4 = __ldg((const float4*)waq + lane);
        float4 wak4 = __ldg((const float4*)wak + lane);
#pragma unroll
        for (int i = 0; i < 8; ++i) {
            const int r = wm * 8 + i;      // 0..127
            float4 a  = __ldg((const float4*)(Wq + r * D_) + lane);
            float4 k4 = __ldg((const float4*)(Wk + r * D_) + lane);
            float sq = dot4(a, waq4);
            float sk = dot4(k4, wak4);
#pragma unroll
            for (int off = 16; off; off >>= 1) {
                sq += __shfl_xor_sync(0xFFFFFFFFu, sq, off);
                sk += __shfl_xor_sync(0xFFFFFFFFu, sk, off);
            }
            if (lane == 0) { uq_s[r] = sq; uk_s[r] = sk; }
        }
        if (wm == 0) {
            float4 xq = __ldg((const float4*)bq + lane);
            float4 xk = __ldg((const float4*)bk + lane);
            float p = dot4(xq, waq4) + dot4(xk, wak4);
#pragma unroll
            for (int off = 16; off; off >>= 1)
                p += __shfl_xor_sync(0xFFFFFFFFu, p, off);
            if (lane == 0) c_s[0] = p + __ldg(ba);
        }
    }
    __syncthreads();   // Wv + uq/uk/c ready

    const int q  = lane >> 3;              // quarter 0..3 (row within group)
    const int qi = lane & 7;               // position in quarter; owns 16 elems

    // lane's 16-element segment of uq/uk (float4 units qi*4 .. qi*4+3)
    float4 uq4[4], uk4[4];
#pragma unroll
    for (int c = 0; c < 4; ++c) {
        uq4[c] = ((const float4*)uq_s)[qi * 4 + c];
        uk4[c] = ((const float4*)uk_s)[qi * 4 + c];
    }
    const float cc = c_s[0];

    float* aw = as_s + wm * 8 * 128;       // warp-private As slice (8 rows)

    // ========== phase 1: attention, 4 rows per warp-iteration ==========
#pragma unroll 1
    for (int it = 0; it < 2; ++it) {
        const int rl  = wm * 8 + it * 4 + q;   // local row 0..127
        const int row = row0 + rl;

        const float4* np = (const float4*)(nbrs + (size_t)row * (K_ * D_));
        const float*  mp = mask + (size_t)row * K_;

        // mask into regs (8 lanes/quarter load same addr -> broadcast)
        float m[K_];
#pragma unroll
        for (int j = 0; j < K_; ++j) m[j] = __ldg(mp + j);

        // node segment (kept for combine)
        float4 nh0[4];
        const float4* nodep = (const float4*)(nodes + (size_t)row * D_);
#pragma unroll
        for (int c = 0; c < 4; ++c) nh0[c] = __ldg(nodep + qi * 4 + c);

        // pass 1: dot partials (lane covers 16 of 128 elements)
        float kd[K_ + 1];
        float qd = dot4(nh0[0], uq4[0]) + dot4(nh0[1], uq4[1])
                 + dot4(nh0[2], uq4[2]) + dot4(nh0[3], uq4[3]);
        kd[0]    = dot4(nh0[0], uk4[0]) + dot4(nh0[1], uk4[1])
                 + dot4(nh0[2], uk4[2]) + dot4(nh0[3], uk4[3]);
#pragma unroll
        for (int j = 0; j < K_; ++j) {
            float acc = 0.f;
#pragma unroll
            for (int c = 0; c < 4; ++c) {
                float4 v = __ldg(np + j * 32 + qi * 4 + c);
                acc += dot4(v, uk4[c]);
            }
            kd[j + 1] = acc;
        }

        // 3-stage butterfly within the 8-lane quarter (serves 4 rows at once)
#pragma unroll
        for (int off = 4; off; off >>= 1) {
            qd += __shfl_xor_sync(0xFFFFFFFFu, qd, off);
#pragma unroll
            for (int j = 0; j <= K_; ++j)
                kd[j] += __shfl_xor_sync(0xFFFFFFFFu, kd[j], off);
        }

        // masked LeakyReLU-exp softmax (redundant across the 8 quarter lanes)
        const float sbase = qd + cc;
        float s = 0.f;
#pragma unroll
        for (int j = 0; j <= K_; ++j) {
            float t = kd[j] + sbase;
            t = (t >= 0.f) ? t : 0.2f * t;
            float ej = __expf(t);
            if (j) ej *= m[j - 1];
            kd[j] = ej;
            s += ej;
        }
        const float inv = 1.f / (s + 1e-16f);
#pragma unroll
        for (int j = 0; j <= K_; ++j) kd[j] *= inv;

        // pass 2: reload neighbor segments (L1 hits) and combine
        float4 w[4];
#pragma unroll
        for (int c = 0; c < 4; ++c) {
            w[c].x = kd[0] * nh0[c].x;
            w[c].y = kd[0] * nh0[c].y;
            w[c].z = kd[0] * nh0[c].z;
            w[c].w = kd[0] * nh0[c].w;
        }
#pragma unroll
        for (int j = 0; j < K_; ++j) {
            const float a = kd[j + 1];
#pragma unroll
            for (int c = 0; c < 4; ++c) {
                float4 v = __ldg(np + j * 32 + qi * 4 + c);
                w[c].x = fmaf(a, v.x, w[c].x);
                w[c].y = fmaf(a, v.y, w[c].y);
                w[c].z = fmaf(a, v.z, w[c].z);
                w[c].w = fmaf(a, v.w, w[c].w);
            }
        }

#pragma unroll
        for (int c = 0; c < 4; ++c)
            ((float4*)(as_s + rl * 128))[qi * 4 + c] = w[c];
        if (qi == 0) ssum_s[rl] = s * inv;
    }

    __syncwarp();      // warp wrote exactly its own 8 rows of as_s + ssum_s

    // ========== phase 2: GEMM 8 rows x 128 cols per warp ==========
    const float* b_base = wv_s + lane * 4;

    unsigned long long acc[8][2];
#pragma unroll
    for (int r = 0; r < 8; ++r) { acc[r][0] = 0ull; acc[r][1] = 0ull; }

#pragma unroll 2
    for (int k = 0; k < 128; k += 4) {
        float4 a4[8];
#pragma unroll
        for (int r = 0; r < 8; ++r)
            a4[r] = *(const float4*)(aw + r * 128 + k);   // broadcast LDS
#pragma unroll
        for (int kk = 0; kk < 4; ++kk) {
            ulonglong2 b = *(const ulonglong2*)(b_base + (k + kk) * 128);
#pragma unroll
            for (int r = 0; r < 8; ++r) {
                float av = (kk == 0) ? a4[r].x : (kk == 1) ? a4[r].y
                         : (kk == 2) ? a4[r].z : a4[r].w;
                unsigned long long ap = pack2(av);
                ffma2(acc[r][0], ap, b.x);
                ffma2(acc[r][1], ap, b.y);
            }
        }
    }

    // epilogue: + asum * bv, coalesced stores
    float4 bv4 = __ldg((const float4*)(bv + lane * 4));
#pragma unroll
    for (int r = 0; r < 8; ++r) {
        const float srow = ssum_s[wm * 8 + r];
        float2 p0 = unpack2(acc[r][0]);
        float2 p1 = unpack2(acc[r][1]);
        float4 o = make_float4(fmaf(srow, bv4.x, p0.x),
                               fmaf(srow, bv4.y, p0.y),
                               fmaf(srow, bv4.z, p1.x),
                               fmaf(srow, bv4.w, p1.y));
        *(float4*)(out + (size_t)(row0 + wm * 8 + r) * D_ + lane * 4) = o;
    }
}

extern "C" void kernel_launch(void* const* d_in, const int* in_sizes, int n_in,
                              void* d_out, int out_size) {
    const float* nodes = (const float*)d_in[0];
    const float* nbrs  = (const float*)d_in[1];
    const float* mask  = (const float*)d_in[2];
    const float* Wq    = (const float*)d_in[3];
    const float* bq    = (const float*)d_in[4];
    const float* Wk    = (const float*)d_in[5];
    const float* bk    = (const float*)d_in[6];
    const float* Wv    = (const float*)d_in[7];
    const float* bv    = (const float*)d_in[8];
    const float* waq   = (const float*)d_in[9];
    const float* wak   = (const float*)d_in[10];
    const float* ba    = (const float*)d_in[11];
    float* out = (float*)d_out;

    cudaFuncSetAttribute(gat_fused, cudaFuncAttributeMaxDynamicSharedMemorySize,
                         F_SM_FLOATS * 4);

    gat_fused<<<ROWS / F_TILE, F_THREADS, F_SM_FLOATS * 4>>>(
        nodes, nbrs, mask, Wq, bq, Wk, bk, Wv, bv, waq, wak, ba, out);
}

// round 14
// speedup vs baseline: 1.4642x; 1.4642x over previous
#include <cuda_runtime.h>

#define B_   256
#define N_   64
#define K_   12
#define D_   128
#define ROWS 16384

#define F_GRID    148
#define F_RPB     111           // rows per block (148*111 = 16428 >= 16384)
#define F_ITERS   7             // 7*16 = 112 >= 111 row slots per block
#define F_THREADS 512
// floats: Wv 16384 + As 112*128 + uq 128 + uk 128 + ssum 112 + c 4
#define F_SM_FLOATS (16384 + 112 * 128 + 128 + 128 + 112 + 4)

__device__ __forceinline__ float dot4(float4 a, float4 b) {
    return fmaf(a.x, b.x, fmaf(a.y, b.y, fmaf(a.z, b.z, a.w * b.w)));
}
__device__ __forceinline__ void ffma2(unsigned long long& d, unsigned long long a, unsigned long long b) {
    asm("fma.rn.f32x2 %0, %1, %2, %0;" : "+l"(d) : "l"(a), "l"(b));
}
__device__ __forceinline__ unsigned long long pack2(float x) {
    unsigned long long r;
    asm("mov.b64 %0, {%1, %1};" : "=l"(r) : "f"(x));
    return r;
}
__device__ __forceinline__ float2 unpack2(unsigned long long v) {
    float2 f;
    asm("mov.b64 {%0, %1}, %2;" : "=f"(f.x), "=f"(f.y) : "l"(v));
    return f;
}

__global__ __launch_bounds__(F_THREADS, 1)
void gat_fused(const float* __restrict__ nodes, const float* __restrict__ nbrs,
               const float* __restrict__ mask,
               const float* __restrict__ Wq, const float* __restrict__ bq,
               const float* __restrict__ Wk, const float* __restrict__ bk,
               const float* __restrict__ Wv, const float* __restrict__ bv,
               const float* __restrict__ waq, const float* __restrict__ wak,
               const float* __restrict__ ba,
               float* __restrict__ out)
{
    extern __shared__ float sm[];
    float* wv_s   = sm;                     // [128][128]
    float* as_s   = sm + 16384;             // [112][128]
    float* uq_s   = as_s + 112 * 128;       // [128]
    float* uk_s   = uq_s + 128;             // [128]
    float* ssum_s = uk_s + 128;             // [112]
    float* c_s    = ssum_s + 112;           // [1]

    const int tid   = threadIdx.x;
    const int lane  = tid & 31;
    const int wm    = tid >> 5;             // 0..15
    const int start = blockIdx.x * F_RPB;
    const int nrows = min(F_RPB, ROWS - start);

    // ---- Wv -> shared (issued first; drains by the syncthreads) ----
    {
        const float4* src = (const float4*)Wv;
        float4* dst = (float4*)wv_s;
#pragma unroll
        for (int i = tid; i < 16384 / 4; i += F_THREADS) dst[i] = src[i];
    }

    // ---- redundant per-block prologue: uq = Wq@waq, uk = Wk@wak, c ----
    {
        float4 waq4 = __ldg((const float4*)waq + lane);
        float4 wak4 = __ldg((const float4*)wak + lane);
#pragma unroll
        for (int i = 0; i < 8; ++i) {
            const int r = wm * 8 + i;       // 0..127
            float4 a  = __ldg((const float4*)(Wq + r * D_) + lane);
            float4 k4 = __ldg((const float4*)(Wk + r * D_) + lane);
            float sq = dot4(a, waq4);
            float sk = dot4(k4, wak4);
#pragma unroll
            for (int off = 16; off; off >>= 1) {
                sq += __shfl_xor_sync(0xFFFFFFFFu, sq, off);
                sk += __shfl_xor_sync(0xFFFFFFFFu, sk, off);
            }
            if (lane == 0) { uq_s[r] = sq; uk_s[r] = sk; }
        }
        if (wm == 0) {
            float4 xq = __ldg((const float4*)bq + lane);
            float4 xk = __ldg((const float4*)bk + lane);
            float p = dot4(xq, waq4) + dot4(xk, wak4);
#pragma unroll
            for (int off = 16; off; off >>= 1)
                p += __shfl_xor_sync(0xFFFFFFFFu, p, off);
            if (lane == 0) c_s[0] = p + __ldg(ba);
        }
    }
    __syncthreads();   // Wv + uq/uk/c ready

    const float4 uq4 = ((const float4*)uq_s)[lane];
    const float4 uk4 = ((const float4*)uk_s)[lane];
    const float  cc  = c_s[0];

    // ========== phase 1: attention; warp owns rows i*16+wm, i<7 ==========
#pragma unroll 1
    for (int i = 0; i < F_ITERS; ++i) {
        const int rl = i * 16 + wm;         // local row slot 0..111
        if (rl < nrows) {
            const int row = start + rl;

            // mask prefetch (12 uniform loads)
            float m[K_];
            const float* mp = mask + (size_t)row * K_;
#pragma unroll
            for (int j = 0; j < K_; ++j) m[j] = __ldg(mp + j);

            // pass 1: coalesced loads, 13 sim partials (qd merged per lane)
            float4 nh0 = __ldg((const float4*)(nodes + (size_t)row * D_) + lane);
            const float4* np = (const float4*)(nbrs + (size_t)row * (K_ * D_));
            float kd[K_ + 1];
            const float qd = dot4(nh0, uq4);      // lane-partial of q-term
            kd[0] = dot4(nh0, uk4) + qd;
#pragma unroll
            for (int j = 0; j < K_; ++j) {
                float4 v = __ldg(np + j * 32 + lane);
                kd[j + 1] = dot4(v, uk4) + qd;
            }

            // butterfly reduce 13 values across the warp
#pragma unroll
            for (int off = 16; off; off >>= 1) {
#pragma unroll
                for (int j = 0; j <= K_; ++j)
                    kd[j] += __shfl_xor_sync(0xFFFFFFFFu, kd[j], off);
            }

            // masked LeakyReLU-exp softmax
            float s = 0.f;
#pragma unroll
            for (int j = 0; j <= K_; ++j) {
                float t = kd[j] + cc;
                t = (t >= 0.f) ? t : 0.2f * t;
                float ej = __expf(t);
                if (j) ej *= m[j - 1];
                kd[j] = ej;
                s += ej;
            }
            const float inv = 1.f / (s + 1e-16f);
#pragma unroll
            for (int j = 0; j <= K_; ++j) kd[j] *= inv;

            // pass 2: reload neighbors (L1 hits) and combine
            float4 w = make_float4(kd[0] * nh0.x, kd[0] * nh0.y,
                                   kd[0] * nh0.z, kd[0] * nh0.w);
#pragma unroll
            for (int j = 0; j < K_; ++j) {
                float4 v = __ldg(np + j * 32 + lane);
                float a = kd[j + 1];
                w.x = fmaf(a, v.x, w.x);
                w.y = fmaf(a, v.y, w.y);
                w.z = fmaf(a, v.z, w.z);
                w.w = fmaf(a, v.w, w.w);
            }

            ((float4*)(as_s + rl * 128))[lane] = w;
            if (lane == 0) ssum_s[rl] = s * inv;
        } else {
            // out-of-range slot: zero so the GEMM stays unguarded
            ((float4*)(as_s + rl * 128))[lane] = make_float4(0.f, 0.f, 0.f, 0.f);
            if (lane == 0) ssum_s[rl] = 0.f;
        }
    }

    __syncwarp();      // warp wrote exactly its own row slots

    // ========== phase 2: GEMM 7 row-slots x 128 cols per warp ==========
    const float* b_base = wv_s + lane * 4;

    unsigned long long acc[F_ITERS][2];
#pragma unroll
    for (int i = 0; i < F_ITERS; ++i) { acc[i][0] = 0ull; acc[i][1] = 0ull; }

#pragma unroll 2
    for (int k = 0; k < 128; k += 4) {
        float4 a4[F_ITERS];
#pragma unroll
        for (int i = 0; i < F_ITERS; ++i)
            a4[i] = *(const float4*)(as_s + (i * 16 + wm) * 128 + k);
#pragma unroll
        for (int kk = 0; kk < 4; ++kk) {
            ulonglong2 b = *(const ulonglong2*)(b_base + (k + kk) * 128);
#pragma unroll
            for (int i = 0; i < F_ITERS; ++i) {
                float av = (kk == 0) ? a4[i].x : (kk == 1) ? a4[i].y
                         : (kk == 2) ? a4[i].z : a4[i].w;
                unsigned long long ap = pack2(av);
                ffma2(acc[i][0], ap, b.x);
                ffma2(acc[i][1], ap, b.y);
            }
        }
    }

    // epilogue: + asum * bv, coalesced stores (guard real rows only)
    float4 bv4 = __ldg((const float4*)(bv + lane * 4));
#pragma unroll
    for (int i = 0; i < F_ITERS; ++i) {
        const int rl = i * 16 + wm;
        if (rl < nrows) {
            const float srow = ssum_s[rl];
            float2 p0 = unpack2(acc[i][0]);
            float2 p1 = unpack2(acc[i][1]);
            float4 o = make_float4(fmaf(srow, bv4.x, p0.x),
                                   fmaf(srow, bv4.y, p0.y),
                                   fmaf(srow, bv4.z, p1.x),
                                   fmaf(srow, bv4.w, p1.y));
            *(float4*)(out + (size_t)(start + rl) * D_ + lane * 4) = o;
        }
    }
}

extern "C" void kernel_launch(void* const* d_in, const int* in_sizes, int n_in,
                              void* d_out, int out_size) {
    const float* nodes = (const float*)d_in[0];
    const float* nbrs  = (const float*)d_in[1];
    const float* mask  = (const float*)d_in[2];
    const float* Wq    = (const float*)d_in[3];
    const float* bq    = (const float*)d_in[4];
    const float* Wk    = (const float*)d_in[5];
    const float* bk    = (const float*)d_in[6];
    const float* Wv    = (const float*)d_in[7];
    const float* bv    = (const float*)d_in[8];
    const float* waq   = (const float*)d_in[9];
    const float* wak   = (const float*)d_in[10];
    const float* ba    = (const float*)d_in[11];
    float* out = (float*)d_out;

    cudaFuncSetAttribute(gat_fused, cudaFuncAttributeMaxDynamicSharedMemorySize,
                         F_SM_FLOATS * 4);

    gat_fused<<<F_GRID, F_THREADS, F_SM_FLOATS * 4>>>(
        nodes, nbrs, mask, Wq, bq, Wk, bk, Wv, bv, waq, wak, ba, out);
}